// round 1
// baseline (speedup 1.0000x reference)
#include <cuda_runtime.h>
#include <cuda_bf16.h>
#include <math.h>

// ---------------------------------------------------------------------------
// EncoderLayer: pre-norm transformer encoder layer, fp32 baseline.
//   B=2, S=2048, D_MODEL=1024, H=16, D_K=64, FF=4096
// Inputs (metadata order):
//   0 x [2,2048,1024] f32      1 mask [2,1,1,2048] i32
//   2 wq 3 wk 4 wv 5 wo [1024,1024]
//   6 bq 7 bk 8 bv 9 bo [1024]
//   10 w1 [1024,4096] 11 b1 [4096] 12 w2 [4096,1024] 13 b2 [1024]
//   14 ln1_g 15 ln1_b 16 ln2_g 17 ln2_b [1024]
// Output: [2,2048,1024] f32
// ---------------------------------------------------------------------------

#define D_MODEL 1024
#define SEQ     2048
#define BATCH   2
#define HEADS   16
#define DK      64
#define FF_DIM  4096
#define MROWS   (BATCH * SEQ)      // 4096

// Scratch (allocation-free: device globals)
__device__ float g_h  [MROWS * D_MODEL];
__device__ float g_q  [MROWS * D_MODEL];
__device__ float g_k  [MROWS * D_MODEL];
__device__ float g_v  [MROWS * D_MODEL];
__device__ float g_ctx[MROWS * D_MODEL];
__device__ float g_x1 [MROWS * D_MODEL];
__device__ float g_h2 [MROWS * D_MODEL];
__device__ float g_ff1[(size_t)MROWS * FF_DIM];

// ---------------------------------------------------------------------------
// LayerNorm: one block (256 threads) per row of 1024.
// ref: g * (x - mean) / (std + eps) + b, std unbiased (ddof=1)
// ---------------------------------------------------------------------------
__global__ void ln_kernel(const float* __restrict__ x,
                          const float* __restrict__ gamma,
                          const float* __restrict__ beta,
                          float* __restrict__ out)
{
    __shared__ float red[8];
    __shared__ float bval[2];
    const int row = blockIdx.x;
    const int tid = threadIdx.x;

    const float4 xv = ((const float4*)(x + (size_t)row * D_MODEL))[tid];

    // --- sum reduce ---
    float s = xv.x + xv.y + xv.z + xv.w;
    #pragma unroll
    for (int o = 16; o; o >>= 1) s += __shfl_xor_sync(0xffffffffu, s, o);
    if ((tid & 31) == 0) red[tid >> 5] = s;
    __syncthreads();
    if (tid < 32) {
        float t = (tid < 8) ? red[tid] : 0.f;
        #pragma unroll
        for (int o = 4; o; o >>= 1) t += __shfl_xor_sync(0xffffffffu, t, o);
        if (tid == 0) bval[0] = t;
    }
    __syncthreads();
    const float mean = bval[0] * (1.f / 1024.f);

    const float d0 = xv.x - mean, d1 = xv.y - mean, d2 = xv.z - mean, d3 = xv.w - mean;
    float ss = d0 * d0 + d1 * d1 + d2 * d2 + d3 * d3;
    #pragma unroll
    for (int o = 16; o; o >>= 1) ss += __shfl_xor_sync(0xffffffffu, ss, o);
    if ((tid & 31) == 0) red[tid >> 5] = ss;
    __syncthreads();
    if (tid < 32) {
        float t = (tid < 8) ? red[tid] : 0.f;
        #pragma unroll
        for (int o = 4; o; o >>= 1) t += __shfl_xor_sync(0xffffffffu, t, o);
        if (tid == 0) bval[1] = t;
    }
    __syncthreads();
    const float var = bval[1] * (1.f / 1023.f);     // ddof=1
    const float inv = 1.f / (sqrtf(var) + 1e-6f);   // (std + eps)

    const float4 gv = ((const float4*)gamma)[tid];
    const float4 bv = ((const float4*)beta)[tid];
    float4 ov;
    ov.x = gv.x * d0 * inv + bv.x;
    ov.y = gv.y * d1 * inv + bv.y;
    ov.z = gv.z * d2 * inv + bv.z;
    ov.w = gv.w * d3 * inv + bv.w;
    ((float4*)(out + (size_t)row * D_MODEL))[tid] = ov;
}

// ---------------------------------------------------------------------------
// SGEMM: C[M,N] = A[M,K] @ W[K,N] + bias (+ residual) (+ relu)
// 64x64 tile, BK=16, 256 threads, 4x4 per thread.
// ---------------------------------------------------------------------------
__global__ void gemm64(const float* __restrict__ A, const float* __restrict__ W,
                       const float* __restrict__ bias, const float* __restrict__ res,
                       float* __restrict__ C, int M, int N, int K, int relu)
{
    __shared__ float As[16][68];
    __shared__ float Bs[16][68];

    const int tid = threadIdx.x;
    const int tx = tid & 15, ty = tid >> 4;
    const int row0 = blockIdx.y * 64, col0 = blockIdx.x * 64;
    const int aRow = tid >> 2, aSeg = tid & 3;
    const int bRow = tid >> 4, bSeg = tid & 15;

    const float* Aptr = A + (size_t)(row0 + aRow) * K + aSeg * 4;
    const float* Wptr = W + (size_t)bRow * N + col0 + bSeg * 4;

    float acc[4][4] = {};

    for (int kt = 0; kt < K; kt += 16) {
        float4 av = *(const float4*)(Aptr + kt);
        As[aSeg * 4 + 0][aRow] = av.x;
        As[aSeg * 4 + 1][aRow] = av.y;
        As[aSeg * 4 + 2][aRow] = av.z;
        As[aSeg * 4 + 3][aRow] = av.w;
        float4 bv = *(const float4*)(Wptr + (size_t)kt * N);
        *(float4*)&Bs[bRow][bSeg * 4] = bv;
        __syncthreads();

        #pragma unroll
        for (int k = 0; k < 16; ++k) {
            float a[4], b[4];
            #pragma unroll
            for (int i = 0; i < 4; ++i) a[i] = As[k][ty * 4 + i];
            #pragma unroll
            for (int j = 0; j < 4; ++j) b[j] = Bs[k][tx * 4 + j];
            #pragma unroll
            for (int i = 0; i < 4; ++i)
                #pragma unroll
                for (int j = 0; j < 4; ++j)
                    acc[i][j] = fmaf(a[i], b[j], acc[i][j]);
        }
        __syncthreads();
    }

    #pragma unroll
    for (int i = 0; i < 4; ++i) {
        const int r = row0 + ty * 4 + i;
        #pragma unroll
        for (int j = 0; j < 4; ++j) {
            const int c = col0 + tx * 4 + j;
            float v = acc[i][j] + bias[c];
            if (res) v += res[(size_t)r * N + c];
            if (relu) v = fmaxf(v, 0.f);
            C[(size_t)r * N + c] = v;
        }
    }
}

// ---------------------------------------------------------------------------
// Flash attention, fp32: Br=Bc=64, d=64.
// grid (S/64, HEADS, BATCH), 256 threads.
// Q/K/V layout: [B, S, H*DK] (head h at column offset h*64).
// ---------------------------------------------------------------------------
#define ATTN_PAD 65
#define ATTN_SMEM_FLOATS (4 * 64 * ATTN_PAD + 3 * 64)

__global__ void attn_kernel(const float* __restrict__ Q, const float* __restrict__ K,
                            const float* __restrict__ V, const int* __restrict__ mask,
                            float* __restrict__ O)
{
    extern __shared__ float sm[];
    float* Qs   = sm;
    float* Ks   = Qs + 64 * ATTN_PAD;
    float* Vs   = Ks + 64 * ATTN_PAD;
    float* Ss   = Vs + 64 * ATTN_PAD;
    float* mrow = Ss + 64 * ATTN_PAD;
    float* lrow = mrow + 64;
    float* srow = lrow + 64;

    const int qt = blockIdx.x;
    const int h  = blockIdx.y;
    const int b  = blockIdx.z;
    const int tid = threadIdx.x;
    const int tx = tid & 15, ty = tid >> 4;
    const int lr = tid >> 2, seg = tid & 3;   // load/softmax: 4 threads per row

    const size_t base = ((size_t)b * SEQ) * D_MODEL + h * DK;

    // load Q tile (scaled by 1/sqrt(64))
    {
        const float* qp = Q + base + (size_t)(qt * 64 + lr) * D_MODEL + seg * 16;
        #pragma unroll
        for (int i = 0; i < 4; ++i) {
            float4 v = *(const float4*)(qp + i * 4);
            const int c = seg * 16 + i * 4;
            Qs[lr * ATTN_PAD + c + 0] = v.x * 0.125f;
            Qs[lr * ATTN_PAD + c + 1] = v.y * 0.125f;
            Qs[lr * ATTN_PAD + c + 2] = v.z * 0.125f;
            Qs[lr * ATTN_PAD + c + 3] = v.w * 0.125f;
        }
    }
    if (tid < 64) { mrow[tid] = -INFINITY; lrow[tid] = 0.f; }

    float acc[4][4] = {};
    __syncthreads();

    for (int j = 0; j < SEQ / 64; ++j) {
        // load K, V tiles
        {
            const float* kp = K + base + (size_t)(j * 64 + lr) * D_MODEL + seg * 16;
            const float* vp = V + base + (size_t)(j * 64 + lr) * D_MODEL + seg * 16;
            #pragma unroll
            for (int i = 0; i < 4; ++i) {
                float4 kv = *(const float4*)(kp + i * 4);
                float4 vv = *(const float4*)(vp + i * 4);
                const int c = seg * 16 + i * 4;
                Ks[lr * ATTN_PAD + c + 0] = kv.x; Ks[lr * ATTN_PAD + c + 1] = kv.y;
                Ks[lr * ATTN_PAD + c + 2] = kv.z; Ks[lr * ATTN_PAD + c + 3] = kv.w;
                Vs[lr * ATTN_PAD + c + 0] = vv.x; Vs[lr * ATTN_PAD + c + 1] = vv.y;
                Vs[lr * ATTN_PAD + c + 2] = vv.z; Vs[lr * ATTN_PAD + c + 3] = vv.w;
            }
        }
        __syncthreads();

        // S = Qs @ Ks^T  (4x4 per thread)
        float s[4][4] = {};
        #pragma unroll
        for (int d = 0; d < 64; ++d) {
            float a[4], c[4];
            #pragma unroll
            for (int i = 0; i < 4; ++i) a[i] = Qs[(ty * 4 + i) * ATTN_PAD + d];
            #pragma unroll
            for (int jj = 0; jj < 4; ++jj) c[jj] = Ks[(tx * 4 + jj) * ATTN_PAD + d];
            #pragma unroll
            for (int i = 0; i < 4; ++i)
                #pragma unroll
                for (int jj = 0; jj < 4; ++jj)
                    s[i][jj] = fmaf(a[i], c[jj], s[i][jj]);
        }
        // mask + store S
        #pragma unroll
        for (int jj = 0; jj < 4; ++jj) {
            const int col = j * 64 + tx * 4 + jj;
            const bool ok = mask[b * SEQ + col] != 0;
            #pragma unroll
            for (int i = 0; i < 4; ++i)
                Ss[(ty * 4 + i) * ATTN_PAD + tx * 4 + jj] = ok ? s[i][jj] : -1.0e9f;
        }
        __syncthreads();

        // online softmax: 4 threads per row (consecutive lanes)
        {
            float mx = -INFINITY;
            #pragma unroll
            for (int c = 0; c < 16; ++c)
                mx = fmaxf(mx, Ss[lr * ATTN_PAD + seg * 16 + c]);
            mx = fmaxf(mx, __shfl_xor_sync(0xffffffffu, mx, 1));
            mx = fmaxf(mx, __shfl_xor_sync(0xffffffffu, mx, 2));
            const float mold = mrow[lr];
            const float mnew = fmaxf(mold, mx);
            float sum = 0.f;
            #pragma unroll
            for (int c = 0; c < 16; ++c) {
                const int idx = lr * ATTN_PAD + seg * 16 + c;
                const float p = expf(Ss[idx] - mnew);
                Ss[idx] = p;
                sum += p;
            }
            sum += __shfl_xor_sync(0xffffffffu, sum, 1);
            sum += __shfl_xor_sync(0xffffffffu, sum, 2);
            if (seg == 0) {
                const float sc = expf(mold - mnew);
                srow[lr] = sc;
                lrow[lr] = lrow[lr] * sc + sum;
                mrow[lr] = mnew;
            }
        }
        __syncthreads();

        // rescale accumulators, then O += P @ V
        #pragma unroll
        for (int i = 0; i < 4; ++i) {
            const float sc = srow[ty * 4 + i];
            #pragma unroll
            for (int jj = 0; jj < 4; ++jj) acc[i][jj] *= sc;
        }
        #pragma unroll
        for (int d = 0; d < 64; ++d) {
            float p[4], v[4];
            #pragma unroll
            for (int i = 0; i < 4; ++i) p[i] = Ss[(ty * 4 + i) * ATTN_PAD + d];
            #pragma unroll
            for (int jj = 0; jj < 4; ++jj) v[jj] = Vs[d * ATTN_PAD + tx * 4 + jj];
            #pragma unroll
            for (int i = 0; i < 4; ++i)
                #pragma unroll
                for (int jj = 0; jj < 4; ++jj)
                    acc[i][jj] = fmaf(p[i], v[jj], acc[i][jj]);
        }
        __syncthreads();
    }

    // epilogue: divide by l, write ctx in [B,S,H*DK]
    #pragma unroll
    for (int i = 0; i < 4; ++i) {
        const int r = ty * 4 + i;
        const float inv = 1.f / lrow[r];
        float* op = O + base + (size_t)(qt * 64 + r) * D_MODEL + tx * 4;
        #pragma unroll
        for (int jj = 0; jj < 4; ++jj) op[jj] = acc[i][jj] * inv;
    }
}

// ---------------------------------------------------------------------------
extern "C" void kernel_launch(void* const* d_in, const int* in_sizes, int n_in,
                              void* d_out, int out_size)
{
    const float* x    = (const float*)d_in[0];
    const int*   mask = (const int*)  d_in[1];
    const float* wq   = (const float*)d_in[2];
    const float* wk   = (const float*)d_in[3];
    const float* wv   = (const float*)d_in[4];
    const float* wo   = (const float*)d_in[5];
    const float* bq   = (const float*)d_in[6];
    const float* bk   = (const float*)d_in[7];
    const float* bv   = (const float*)d_in[8];
    const float* bo   = (const float*)d_in[9];
    const float* w1   = (const float*)d_in[10];
    const float* b1   = (const float*)d_in[11];
    const float* w2   = (const float*)d_in[12];
    const float* b2   = (const float*)d_in[13];
    const float* ln1g = (const float*)d_in[14];
    const float* ln1b = (const float*)d_in[15];
    const float* ln2g = (const float*)d_in[16];
    const float* ln2b = (const float*)d_in[17];
    float* out = (float*)d_out;

    void *p;
    cudaGetSymbolAddress(&p, g_h);   float* h   = (float*)p;
    cudaGetSymbolAddress(&p, g_q);   float* q   = (float*)p;
    cudaGetSymbolAddress(&p, g_k);   float* k   = (float*)p;
    cudaGetSymbolAddress(&p, g_v);   float* v   = (float*)p;
    cudaGetSymbolAddress(&p, g_ctx); float* ctx = (float*)p;
    cudaGetSymbolAddress(&p, g_x1);  float* x1  = (float*)p;
    cudaGetSymbolAddress(&p, g_h2);  float* h2  = (float*)p;
    cudaGetSymbolAddress(&p, g_ff1); float* ff1 = (float*)p;

    const int attn_smem = ATTN_SMEM_FLOATS * sizeof(float);
    cudaFuncSetAttribute(attn_kernel, cudaFuncAttributeMaxDynamicSharedMemorySize, attn_smem);

    // 1) h = LN1(x)
    ln_kernel<<<MROWS, 256>>>(x, ln1g, ln1b, h);

    // 2) q,k,v projections
    {
        dim3 grid(D_MODEL / 64, MROWS / 64);
        gemm64<<<grid, 256>>>(h, wq, bq, nullptr, q, MROWS, D_MODEL, D_MODEL, 0);
        gemm64<<<grid, 256>>>(h, wk, bk, nullptr, k, MROWS, D_MODEL, D_MODEL, 0);
        gemm64<<<grid, 256>>>(h, wv, bv, nullptr, v, MROWS, D_MODEL, D_MODEL, 0);
    }

    // 3) attention -> ctx
    {
        dim3 grid(SEQ / 64, HEADS, BATCH);
        attn_kernel<<<grid, 256, attn_smem>>>(q, k, v, mask, ctx);
    }

    // 4) x1 = x + ctx @ wo + bo
    {
        dim3 grid(D_MODEL / 64, MROWS / 64);
        gemm64<<<grid, 256>>>(ctx, wo, bo, x, x1, MROWS, D_MODEL, D_MODEL, 0);
    }

    // 5) h2 = LN2(x1)
    ln_kernel<<<MROWS, 256>>>(x1, ln2g, ln2b, h2);

    // 6) ff1 = relu(h2 @ w1 + b1)
    {
        dim3 grid(FF_DIM / 64, MROWS / 64);
        gemm64<<<grid, 256>>>(h2, w1, b1, nullptr, ff1, MROWS, FF_DIM, D_MODEL, 1);
    }

    // 7) out = x1 + ff1 @ w2 + b2
    {
        dim3 grid(D_MODEL / 64, MROWS / 64);
        gemm64<<<grid, 256>>>(ff1, w2, b2, x1, out, MROWS, D_MODEL, FF_DIM, 0);
    }
}

// round 3
// speedup vs baseline: 2.0250x; 2.0250x over previous
#include <cuda_runtime.h>
#include <cuda_bf16.h>
#include <math.h>
#include <stdint.h>

// ---------------------------------------------------------------------------
// EncoderLayer round 3: GEMMs on mma.sync tf32 (legacy HMMA path — tcgen05
// not available at the harness's compute_103 PTX target). Attention fp32 SIMT.
//   B=2, S=2048, D_MODEL=1024, H=16, D_K=64, FF=4096
// ---------------------------------------------------------------------------

#define D_MODEL 1024
#define SEQ     2048
#define BATCH   2
#define HEADS   16
#define DK      64
#define FF_DIM  4096
#define MROWS   (BATCH * SEQ)      // 4096

// Scratch (allocation-free: device globals)
__device__ float g_h  [MROWS * D_MODEL];
__device__ float g_q  [MROWS * D_MODEL];
__device__ float g_k  [MROWS * D_MODEL];
__device__ float g_v  [MROWS * D_MODEL];
__device__ float g_ctx[MROWS * D_MODEL];
__device__ float g_x1 [MROWS * D_MODEL];
__device__ float g_h2 [MROWS * D_MODEL];
__device__ float g_ff1[(size_t)MROWS * FF_DIM];
// tf32-rounded weight copies
__device__ float g_wqr[D_MODEL * D_MODEL];
__device__ float g_wkr[D_MODEL * D_MODEL];
__device__ float g_wvr[D_MODEL * D_MODEL];
__device__ float g_wor[D_MODEL * D_MODEL];
__device__ float g_w1r[D_MODEL * FF_DIM];
__device__ float g_w2r[FF_DIM * D_MODEL];

__device__ __forceinline__ float to_tf32(float x) {
    float r;
    asm("cvt.rna.tf32.f32 %0, %1;" : "=f"(r) : "f"(x));
    return r;
}
__device__ __forceinline__ uint32_t smem_u32(const void* p) {
    uint32_t a;
    asm("{ .reg .u64 t; cvta.to.shared.u64 t, %1; cvt.u32.u64 %0, t; }" : "=r"(a) : "l"(p));
    return a;
}
#define CP_ASYNC16(sa, gp) \
    asm volatile("cp.async.cg.shared.global [%0], [%1], 16;" :: "r"(sa), "l"(gp) : "memory")
#define CP_COMMIT() asm volatile("cp.async.commit_group;" ::: "memory")
#define CP_WAIT0()  asm volatile("cp.async.wait_group 0;" ::: "memory")
#define CP_WAIT1()  asm volatile("cp.async.wait_group 1;" ::: "memory")

// ---------------------------------------------------------------------------
// tf32 rounding pre-pass (weights)
// ---------------------------------------------------------------------------
__global__ void round_tf32_kernel(const float* __restrict__ in, float* __restrict__ out, int n4)
{
    const int i = blockIdx.x * blockDim.x + threadIdx.x;
    if (i < n4) {
        float4 v = ((const float4*)in)[i];
        v.x = to_tf32(v.x); v.y = to_tf32(v.y); v.z = to_tf32(v.z); v.w = to_tf32(v.w);
        ((float4*)out)[i] = v;
    }
}

// ---------------------------------------------------------------------------
// LayerNorm (rounds its output to tf32: output feeds only mma operands)
// ---------------------------------------------------------------------------
__global__ void ln_kernel(const float* __restrict__ x,
                          const float* __restrict__ gamma,
                          const float* __restrict__ beta,
                          float* __restrict__ out)
{
    __shared__ float red[8];
    __shared__ float bval[2];
    const int row = blockIdx.x;
    const int tid = threadIdx.x;

    const float4 xv = ((const float4*)(x + (size_t)row * D_MODEL))[tid];

    float s = xv.x + xv.y + xv.z + xv.w;
    #pragma unroll
    for (int o = 16; o; o >>= 1) s += __shfl_xor_sync(0xffffffffu, s, o);
    if ((tid & 31) == 0) red[tid >> 5] = s;
    __syncthreads();
    if (tid < 32) {
        float t = (tid < 8) ? red[tid] : 0.f;
        #pragma unroll
        for (int o = 4; o; o >>= 1) t += __shfl_xor_sync(0xffffffffu, t, o);
        if (tid == 0) bval[0] = t;
    }
    __syncthreads();
    const float mean = bval[0] * (1.f / 1024.f);

    const float d0 = xv.x - mean, d1 = xv.y - mean, d2 = xv.z - mean, d3 = xv.w - mean;
    float ss = d0 * d0 + d1 * d1 + d2 * d2 + d3 * d3;
    #pragma unroll
    for (int o = 16; o; o >>= 1) ss += __shfl_xor_sync(0xffffffffu, ss, o);
    if ((tid & 31) == 0) red[tid >> 5] = ss;
    __syncthreads();
    if (tid < 32) {
        float t = (tid < 8) ? red[tid] : 0.f;
        #pragma unroll
        for (int o = 4; o; o >>= 1) t += __shfl_xor_sync(0xffffffffu, t, o);
        if (tid == 0) bval[1] = t;
    }
    __syncthreads();
    const float var = bval[1] * (1.f / 1023.f);
    const float inv = 1.f / (sqrtf(var) + 1e-6f);

    const float4 gv = ((const float4*)gamma)[tid];
    const float4 bv = ((const float4*)beta)[tid];
    float4 ov;
    ov.x = to_tf32(gv.x * d0 * inv + bv.x);
    ov.y = to_tf32(gv.y * d1 * inv + bv.y);
    ov.z = to_tf32(gv.z * d2 * inv + bv.z);
    ov.w = to_tf32(gv.w * d3 * inv + bv.w);
    ((float4*)(out + (size_t)row * D_MODEL))[tid] = ov;
}

// ---------------------------------------------------------------------------
// tf32 mma.sync GEMM: C[M,N] = A[M,K] @ W[K,N] + bias (+res)(+relu)(+round)
// 128x128 tile, BK=32, 256 threads (8 warps of 64x32), cp.async double-buffer.
// Operands must already be tf32-valued in GMEM.
// flags: bit0 = relu, bit1 = round output to tf32
// ---------------------------------------------------------------------------
#define AS_STRIDE 36
#define BS_STRIDE 132
#define AS_BUF (128 * AS_STRIDE)           // floats
#define BS_BUF (32 * BS_STRIDE)
#define GM_SMEM ((2 * AS_BUF + 2 * BS_BUF) * 4)

__global__ void __launch_bounds__(256, 2)
gemm_mma(const float* __restrict__ A, const float* __restrict__ W,
         const float* __restrict__ bias, const float* __restrict__ res,
         float* __restrict__ C, int M, int N, int K, int flags)
{
    extern __shared__ float smf[];
    float* Asf = smf;                       // [2][128][36]
    float* Bsf = smf + 2 * AS_BUF;          // [2][32][132]
    const uint32_t aSm = smem_u32(Asf);
    const uint32_t bSm = smem_u32(Bsf);

    const int tid = threadIdx.x;
    const int lane = tid & 31;
    const int wid = tid >> 5;
    const int g  = lane >> 2;               // 0..7
    const int tg = lane & 3;                // 0..3
    const int wm = (wid & 1) * 64;
    const int wn = (wid >> 1) * 32;
    const int row0 = blockIdx.y * 128;
    const int col0 = blockIdx.x * 128;

    // producer element assignments
    const int ar[4] = { (tid) >> 3, (tid + 256) >> 3, (tid + 512) >> 3, (tid + 768) >> 3 };
    const int aq = (tid & 7) * 4;
    const int bkr[4] = { tid >> 5, (tid + 256) >> 5, (tid + 512) >> 5, (tid + 768) >> 5 };
    const int bq = (tid & 31) * 4;

    float acc[4][4][4] = {};

    const int NC = K >> 5;
    // prologue: chunk 0
    {
        #pragma unroll
        for (int f = 0; f < 4; ++f) {
            CP_ASYNC16(aSm + (uint32_t)(ar[f] * AS_STRIDE + aq) * 4,
                       A + (size_t)(row0 + ar[f]) * K + aq);
            CP_ASYNC16(bSm + (uint32_t)(bkr[f] * BS_STRIDE + bq) * 4,
                       W + (size_t)bkr[f] * N + col0 + bq);
        }
        CP_COMMIT();
    }

    for (int c = 0; c < NC; ++c) {
        const int buf = c & 1;
        __syncthreads();   // protect buffer (c+1)&1 from overwrite before issue
        if (c + 1 < NC) {
            const int kc = (c + 1) << 5;
            const uint32_t aOff = aSm + (uint32_t)(((c + 1) & 1) * AS_BUF) * 4;
            const uint32_t bOff = bSm + (uint32_t)(((c + 1) & 1) * BS_BUF) * 4;
            #pragma unroll
            for (int f = 0; f < 4; ++f) {
                CP_ASYNC16(aOff + (uint32_t)(ar[f] * AS_STRIDE + aq) * 4,
                           A + (size_t)(row0 + ar[f]) * K + kc + aq);
                CP_ASYNC16(bOff + (uint32_t)(bkr[f] * BS_STRIDE + bq) * 4,
                           W + (size_t)(kc + bkr[f]) * N + col0 + bq);
            }
            CP_COMMIT();
            CP_WAIT1();
        } else {
            CP_WAIT0();
        }
        __syncthreads();

        const uint32_t* Au = (const uint32_t*)(Asf + buf * AS_BUF);
        const uint32_t* Bu = (const uint32_t*)(Bsf + buf * BS_BUF);

        #pragma unroll
        for (int s = 0; s < 4; ++s) {
            const int k0 = s * 8;
            uint32_t a[4][4], b[4][2];
            #pragma unroll
            for (int mt = 0; mt < 4; ++mt) {
                const int r = wm + mt * 16 + g;
                a[mt][0] = Au[r * AS_STRIDE + k0 + tg];
                a[mt][1] = Au[(r + 8) * AS_STRIDE + k0 + tg];
                a[mt][2] = Au[r * AS_STRIDE + k0 + tg + 4];
                a[mt][3] = Au[(r + 8) * AS_STRIDE + k0 + tg + 4];
            }
            #pragma unroll
            for (int nt = 0; nt < 4; ++nt) {
                const int ncol = wn + nt * 8 + g;
                b[nt][0] = Bu[(k0 + tg) * BS_STRIDE + ncol];
                b[nt][1] = Bu[(k0 + tg + 4) * BS_STRIDE + ncol];
            }
            #pragma unroll
            for (int mt = 0; mt < 4; ++mt)
                #pragma unroll
                for (int nt = 0; nt < 4; ++nt)
                    asm volatile(
                        "mma.sync.aligned.m16n8k8.row.col.f32.tf32.tf32.f32 "
                        "{%0,%1,%2,%3}, {%4,%5,%6,%7}, {%8,%9}, {%0,%1,%2,%3};"
                        : "+f"(acc[mt][nt][0]), "+f"(acc[mt][nt][1]),
                          "+f"(acc[mt][nt][2]), "+f"(acc[mt][nt][3])
                        : "r"(a[mt][0]), "r"(a[mt][1]), "r"(a[mt][2]), "r"(a[mt][3]),
                          "r"(b[nt][0]), "r"(b[nt][1]));
        }
    }

    // epilogue
    const int relu = flags & 1;
    const int rnd  = flags & 2;
    #pragma unroll
    for (int mt = 0; mt < 4; ++mt) {
        const int r0 = row0 + wm + mt * 16 + g;
        #pragma unroll
        for (int nt = 0; nt < 4; ++nt) {
            const int cc = col0 + wn + nt * 8 + tg * 2;
            float2 bv = *(const float2*)(bias + cc);
            float v0 = acc[mt][nt][0] + bv.x;
            float v1 = acc[mt][nt][1] + bv.y;
            float v2 = acc[mt][nt][2] + bv.x;
            float v3 = acc[mt][nt][3] + bv.y;
            if (res) {
                float2 r1 = *(const float2*)(res + (size_t)r0 * N + cc);
                float2 r2 = *(const float2*)(res + (size_t)(r0 + 8) * N + cc);
                v0 += r1.x; v1 += r1.y; v2 += r2.x; v3 += r2.y;
            }
            if (relu) {
                v0 = fmaxf(v0, 0.f); v1 = fmaxf(v1, 0.f);
                v2 = fmaxf(v2, 0.f); v3 = fmaxf(v3, 0.f);
            }
            if (rnd) {
                v0 = to_tf32(v0); v1 = to_tf32(v1);
                v2 = to_tf32(v2); v3 = to_tf32(v3);
            }
            *(float2*)(C + (size_t)r0 * N + cc) = make_float2(v0, v1);
            *(float2*)(C + (size_t)(r0 + 8) * N + cc) = make_float2(v2, v3);
        }
    }
}

// ---------------------------------------------------------------------------
// Flash attention, fp32: Br=Bc=64, d=64. grid (S/64, HEADS, BATCH), 256 thr.
// Output rounded to tf32 (feeds the wo GEMM).
// ---------------------------------------------------------------------------
#define ATTN_PAD 65
#define ATTN_SMEM_FLOATS (4 * 64 * ATTN_PAD + 3 * 64)

__global__ void attn_kernel(const float* __restrict__ Q, const float* __restrict__ K,
                            const float* __restrict__ V, const int* __restrict__ mask,
                            float* __restrict__ O)
{
    extern __shared__ float smf[];
    float* Qs   = smf;
    float* Ks   = Qs + 64 * ATTN_PAD;
    float* Vs   = Ks + 64 * ATTN_PAD;
    float* Ss   = Vs + 64 * ATTN_PAD;
    float* mrow = Ss + 64 * ATTN_PAD;
    float* lrow = mrow + 64;
    float* srow = lrow + 64;

    const int qt = blockIdx.x;
    const int h  = blockIdx.y;
    const int b  = blockIdx.z;
    const int tid = threadIdx.x;
    const int tx = tid & 15, ty = tid >> 4;
    const int lr = tid >> 2, seg = tid & 3;

    const size_t base = ((size_t)b * SEQ) * D_MODEL + h * DK;

    {
        const float* qp = Q + base + (size_t)(qt * 64 + lr) * D_MODEL + seg * 16;
        #pragma unroll
        for (int i = 0; i < 4; ++i) {
            float4 v = *(const float4*)(qp + i * 4);
            const int c = seg * 16 + i * 4;
            Qs[lr * ATTN_PAD + c + 0] = v.x * 0.125f;
            Qs[lr * ATTN_PAD + c + 1] = v.y * 0.125f;
            Qs[lr * ATTN_PAD + c + 2] = v.z * 0.125f;
            Qs[lr * ATTN_PAD + c + 3] = v.w * 0.125f;
        }
    }
    if (tid < 64) { mrow[tid] = -INFINITY; lrow[tid] = 0.f; }

    float acc[4][4] = {};
    __syncthreads();

    for (int j = 0; j < SEQ / 64; ++j) {
        {
            const float* kp = K + base + (size_t)(j * 64 + lr) * D_MODEL + seg * 16;
            const float* vp = V + base + (size_t)(j * 64 + lr) * D_MODEL + seg * 16;
            #pragma unroll
            for (int i = 0; i < 4; ++i) {
                float4 kv = *(const float4*)(kp + i * 4);
                float4 vv = *(const float4*)(vp + i * 4);
                const int c = seg * 16 + i * 4;
                Ks[lr * ATTN_PAD + c + 0] = kv.x; Ks[lr * ATTN_PAD + c + 1] = kv.y;
                Ks[lr * ATTN_PAD + c + 2] = kv.z; Ks[lr * ATTN_PAD + c + 3] = kv.w;
                Vs[lr * ATTN_PAD + c + 0] = vv.x; Vs[lr * ATTN_PAD + c + 1] = vv.y;
                Vs[lr * ATTN_PAD + c + 2] = vv.z; Vs[lr * ATTN_PAD + c + 3] = vv.w;
            }
        }
        __syncthreads();

        float s[4][4] = {};
        #pragma unroll
        for (int d = 0; d < 64; ++d) {
            float a[4], c[4];
            #pragma unroll
            for (int i = 0; i < 4; ++i) a[i] = Qs[(ty * 4 + i) * ATTN_PAD + d];
            #pragma unroll
            for (int jj = 0; jj < 4; ++jj) c[jj] = Ks[(tx * 4 + jj) * ATTN_PAD + d];
            #pragma unroll
            for (int i = 0; i < 4; ++i)
                #pragma unroll
                for (int jj = 0; jj < 4; ++jj)
                    s[i][jj] = fmaf(a[i], c[jj], s[i][jj]);
        }
        #pragma unroll
        for (int jj = 0; jj < 4; ++jj) {
            const int col = j * 64 + tx * 4 + jj;
            const bool ok = mask[b * SEQ + col] != 0;
            #pragma unroll
            for (int i = 0; i < 4; ++i)
                Ss[(ty * 4 + i) * ATTN_PAD + tx * 4 + jj] = ok ? s[i][jj] : -1.0e9f;
        }
        __syncthreads();

        {
            float mx = -INFINITY;
            #pragma unroll
            for (int c = 0; c < 16; ++c)
                mx = fmaxf(mx, Ss[lr * ATTN_PAD + seg * 16 + c]);
            mx = fmaxf(mx, __shfl_xor_sync(0xffffffffu, mx, 1));
            mx = fmaxf(mx, __shfl_xor_sync(0xffffffffu, mx, 2));
            const float mold = mrow[lr];
            const float mnew = fmaxf(mold, mx);
            float sum = 0.f;
            #pragma unroll
            for (int c = 0; c < 16; ++c) {
                const int idx = lr * ATTN_PAD + seg * 16 + c;
                const float p = expf(Ss[idx] - mnew);
                Ss[idx] = p;
                sum += p;
            }
            sum += __shfl_xor_sync(0xffffffffu, sum, 1);
            sum += __shfl_xor_sync(0xffffffffu, sum, 2);
            if (seg == 0) {
                const float sc = expf(mold - mnew);
                srow[lr] = sc;
                lrow[lr] = lrow[lr] * sc + sum;
                mrow[lr] = mnew;
            }
        }
        __syncthreads();

        #pragma unroll
        for (int i = 0; i < 4; ++i) {
            const float sc = srow[ty * 4 + i];
            #pragma unroll
            for (int jj = 0; jj < 4; ++jj) acc[i][jj] *= sc;
        }
        #pragma unroll
        for (int d = 0; d < 64; ++d) {
            float p[4], v[4];
            #pragma unroll
            for (int i = 0; i < 4; ++i) p[i] = Ss[(ty * 4 + i) * ATTN_PAD + d];
            #pragma unroll
            for (int jj = 0; jj < 4; ++jj) v[jj] = Vs[d * ATTN_PAD + tx * 4 + jj];
            #pragma unroll
            for (int i = 0; i < 4; ++i)
                #pragma unroll
                for (int jj = 0; jj < 4; ++jj)
                    acc[i][jj] = fmaf(p[i], v[jj], acc[i][jj]);
        }
        __syncthreads();
    }

    #pragma unroll
    for (int i = 0; i < 4; ++i) {
        const int r = ty * 4 + i;
        const float inv = 1.f / lrow[r];
        float* op = O + base + (size_t)(qt * 64 + r) * D_MODEL + tx * 4;
        #pragma unroll
        for (int jj = 0; jj < 4; ++jj) op[jj] = to_tf32(acc[i][jj] * inv);
    }
}

// ---------------------------------------------------------------------------
extern "C" void kernel_launch(void* const* d_in, const int* in_sizes, int n_in,
                              void* d_out, int out_size)
{
    const float* x    = (const float*)d_in[0];
    const int*   mask = (const int*)  d_in[1];
    const float* wq   = (const float*)d_in[2];
    const float* wk   = (const float*)d_in[3];
    const float* wv   = (const float*)d_in[4];
    const float* wo   = (const float*)d_in[5];
    const float* bq   = (const float*)d_in[6];
    const float* bk   = (const float*)d_in[7];
    const float* bv   = (const float*)d_in[8];
    const float* bo   = (const float*)d_in[9];
    const float* w1   = (const float*)d_in[10];
    const float* b1   = (const float*)d_in[11];
    const float* w2   = (const float*)d_in[12];
    const float* b2   = (const float*)d_in[13];
    const float* ln1g = (const float*)d_in[14];
    const float* ln1b = (const float*)d_in[15];
    const float* ln2g = (const float*)d_in[16];
    const float* ln2b = (const float*)d_in[17];
    float* out = (float*)d_out;

    void *p;
    cudaGetSymbolAddress(&p, g_h);   float* h   = (float*)p;
    cudaGetSymbolAddress(&p, g_q);   float* q   = (float*)p;
    cudaGetSymbolAddress(&p, g_k);   float* k   = (float*)p;
    cudaGetSymbolAddress(&p, g_v);   float* v   = (float*)p;
    cudaGetSymbolAddress(&p, g_ctx); float* ctx = (float*)p;
    cudaGetSymbolAddress(&p, g_x1);  float* x1  = (float*)p;
    cudaGetSymbolAddress(&p, g_h2);  float* h2  = (float*)p;
    cudaGetSymbolAddress(&p, g_ff1); float* ff1 = (float*)p;
    cudaGetSymbolAddress(&p, g_wqr); float* wqr = (float*)p;
    cudaGetSymbolAddress(&p, g_wkr); float* wkr = (float*)p;
    cudaGetSymbolAddress(&p, g_wvr); float* wvr = (float*)p;
    cudaGetSymbolAddress(&p, g_wor); float* wor = (float*)p;
    cudaGetSymbolAddress(&p, g_w1r); float* w1r = (float*)p;
    cudaGetSymbolAddress(&p, g_w2r); float* w2r = (float*)p;

    const int attn_smem = ATTN_SMEM_FLOATS * sizeof(float);
    cudaFuncSetAttribute(attn_kernel, cudaFuncAttributeMaxDynamicSharedMemorySize, attn_smem);
    cudaFuncSetAttribute(gemm_mma,   cudaFuncAttributeMaxDynamicSharedMemorySize, GM_SMEM);

    // 0) round weights to tf32
    {
        const int TPB = 256;
        const int n1 = D_MODEL * D_MODEL / 4;
        const int n2 = D_MODEL * FF_DIM / 4;
        round_tf32_kernel<<<(n1 + TPB - 1) / TPB, TPB>>>(wq, wqr, n1);
        round_tf32_kernel<<<(n1 + TPB - 1) / TPB, TPB>>>(wk, wkr, n1);
        round_tf32_kernel<<<(n1 + TPB - 1) / TPB, TPB>>>(wv, wvr, n1);
        round_tf32_kernel<<<(n1 + TPB - 1) / TPB, TPB>>>(wo, wor, n1);
        round_tf32_kernel<<<(n2 + TPB - 1) / TPB, TPB>>>(w1, w1r, n2);
        round_tf32_kernel<<<(n2 + TPB - 1) / TPB, TPB>>>(w2, w2r, n2);
    }

    // 1) h = LN1(x)  (tf32-rounded output)
    ln_kernel<<<MROWS, 256>>>(x, ln1g, ln1b, h);

    // 2) q,k,v projections
    {
        dim3 grid(D_MODEL / 128, MROWS / 128);
        gemm_mma<<<grid, 256, GM_SMEM>>>(h, wqr, bq, nullptr, q, MROWS, D_MODEL, D_MODEL, 0);
        gemm_mma<<<grid, 256, GM_SMEM>>>(h, wkr, bk, nullptr, k, MROWS, D_MODEL, D_MODEL, 0);
        gemm_mma<<<grid, 256, GM_SMEM>>>(h, wvr, bv, nullptr, v, MROWS, D_MODEL, D_MODEL, 0);
    }

    // 3) attention -> ctx (tf32-rounded output)
    {
        dim3 grid(SEQ / 64, HEADS, BATCH);
        attn_kernel<<<grid, 256, attn_smem>>>(q, k, v, mask, ctx);
    }

    // 4) x1 = x + ctx @ wo + bo
    {
        dim3 grid(D_MODEL / 128, MROWS / 128);
        gemm_mma<<<grid, 256, GM_SMEM>>>(ctx, wor, bo, x, x1, MROWS, D_MODEL, D_MODEL, 0);
    }

    // 5) h2 = LN2(x1)  (tf32-rounded output)
    ln_kernel<<<MROWS, 256>>>(x1, ln2g, ln2b, h2);

    // 6) ff1 = relu(h2 @ w1 + b1)  (tf32-rounded output)
    {
        dim3 grid(FF_DIM / 128, MROWS / 128);
        gemm_mma<<<grid, 256, GM_SMEM>>>(h2, w1r, b1, nullptr, ff1, MROWS, FF_DIM, D_MODEL, 3);
    }

    // 7) out = x1 + ff1 @ w2 + b2
    {
        dim3 grid(D_MODEL / 128, MROWS / 128);
        gemm_mma<<<grid, 256, GM_SMEM>>>(ff1, w2r, b2, x1, out, MROWS, D_MODEL, FF_DIM, 0);
    }
}

// round 4
// speedup vs baseline: 3.3405x; 1.6496x over previous
#include <cuda_runtime.h>
#include <cuda_bf16.h>
#include <math.h>
#include <stdint.h>

// ---------------------------------------------------------------------------
// EncoderLayer round 4: GEMMs + attention on mma.sync tf32 (HMMA).
//   B=2, S=2048, D_MODEL=1024, H=16, D_K=64, FF=4096
// ---------------------------------------------------------------------------

#define D_MODEL 1024
#define SEQ     2048
#define BATCH   2
#define HEADS   16
#define DK      64
#define FF_DIM  4096
#define MROWS   (BATCH * SEQ)      // 4096
#define QKV_N   (3 * D_MODEL)      // 3072

// Scratch (allocation-free: device globals)
__device__ float g_h   [MROWS * D_MODEL];
__device__ float g_qkv [(size_t)MROWS * QKV_N];
__device__ float g_ctx [MROWS * D_MODEL];
__device__ float g_x1  [MROWS * D_MODEL];
__device__ float g_h2  [MROWS * D_MODEL];
__device__ float g_ff1 [(size_t)MROWS * FF_DIM];
// tf32-rounded weights
__device__ float g_wqkv[(size_t)D_MODEL * QKV_N];
__device__ float g_bqkv[QKV_N];
__device__ float g_wor [D_MODEL * D_MODEL];
__device__ float g_w1r [D_MODEL * FF_DIM];
__device__ float g_w2r [FF_DIM * D_MODEL];

__device__ __forceinline__ float to_tf32(float x) {
    float r;
    asm("cvt.rna.tf32.f32 %0, %1;" : "=f"(r) : "f"(x));
    return r;
}
__device__ __forceinline__ uint32_t smem_u32(const void* p) {
    uint32_t a;
    asm("{ .reg .u64 t; cvta.to.shared.u64 t, %1; cvt.u32.u64 %0, t; }" : "=r"(a) : "l"(p));
    return a;
}
__device__ __forceinline__ void mma_tf32(float* c, uint32_t a0, uint32_t a1,
                                         uint32_t a2, uint32_t a3,
                                         uint32_t b0, uint32_t b1) {
    asm volatile(
        "mma.sync.aligned.m16n8k8.row.col.f32.tf32.tf32.f32 "
        "{%0,%1,%2,%3}, {%4,%5,%6,%7}, {%8,%9}, {%0,%1,%2,%3};"
        : "+f"(c[0]), "+f"(c[1]), "+f"(c[2]), "+f"(c[3])
        : "r"(a0), "r"(a1), "r"(a2), "r"(a3), "r"(b0), "r"(b1));
}
#define CP_ASYNC16(sa, gp) \
    asm volatile("cp.async.cg.shared.global [%0], [%1], 16;" :: "r"(sa), "l"(gp) : "memory")
#define CP_COMMIT() asm volatile("cp.async.commit_group;" ::: "memory")
#define CP_WAIT0()  asm volatile("cp.async.wait_group 0;" ::: "memory")
#define CP_WAIT1()  asm volatile("cp.async.wait_group 1;" ::: "memory")

// ---------------------------------------------------------------------------
// Prepass: tf32 rounding (plain) + packed rounding (QKV) + bias pack
// ---------------------------------------------------------------------------
__global__ void round_tf32_kernel(const float* __restrict__ in, float* __restrict__ out, int n4)
{
    const int i = blockIdx.x * blockDim.x + threadIdx.x;
    if (i < n4) {
        float4 v = ((const float4*)in)[i];
        v.x = to_tf32(v.x); v.y = to_tf32(v.y); v.z = to_tf32(v.z); v.w = to_tf32(v.w);
        ((float4*)out)[i] = v;
    }
}
// in: [rows][nin] -> out slice cols [colOff, colOff+nin) of [rows][ntot]
__global__ void round_pack_kernel(const float* __restrict__ in, float* __restrict__ out,
                                  int rows, int nin, int ntot, int colOff)
{
    const int n4r = nin >> 2;
    const int i = blockIdx.x * blockDim.x + threadIdx.x;
    if (i < rows * n4r) {
        const int k = i / n4r, n4 = i - k * n4r;
        float4 v = ((const float4*)in)[i];
        v.x = to_tf32(v.x); v.y = to_tf32(v.y); v.z = to_tf32(v.z); v.w = to_tf32(v.w);
        *(float4*)(out + (size_t)k * ntot + colOff + n4 * 4) = v;
    }
}
__global__ void pack_bias_kernel(const float* __restrict__ bq, const float* __restrict__ bk,
                                 const float* __restrict__ bv, float* __restrict__ out)
{
    const int i = blockIdx.x * blockDim.x + threadIdx.x;
    if (i < D_MODEL) {
        out[i] = bq[i];
        out[D_MODEL + i] = bk[i];
        out[2 * D_MODEL + i] = bv[i];
    }
}

// ---------------------------------------------------------------------------
// LayerNorm (output rounded to tf32 — feeds mma A operand only)
// ---------------------------------------------------------------------------
__global__ void ln_kernel(const float* __restrict__ x,
                          const float* __restrict__ gamma,
                          const float* __restrict__ beta,
                          float* __restrict__ out)
{
    __shared__ float red[8];
    __shared__ float bval[2];
    const int row = blockIdx.x;
    const int tid = threadIdx.x;

    const float4 xv = ((const float4*)(x + (size_t)row * D_MODEL))[tid];

    float s = xv.x + xv.y + xv.z + xv.w;
    #pragma unroll
    for (int o = 16; o; o >>= 1) s += __shfl_xor_sync(0xffffffffu, s, o);
    if ((tid & 31) == 0) red[tid >> 5] = s;
    __syncthreads();
    if (tid < 32) {
        float t = (tid < 8) ? red[tid] : 0.f;
        #pragma unroll
        for (int o = 4; o; o >>= 1) t += __shfl_xor_sync(0xffffffffu, t, o);
        if (tid == 0) bval[0] = t;
    }
    __syncthreads();
    const float mean = bval[0] * (1.f / 1024.f);

    const float d0 = xv.x - mean, d1 = xv.y - mean, d2 = xv.z - mean, d3 = xv.w - mean;
    float ss = d0 * d0 + d1 * d1 + d2 * d2 + d3 * d3;
    #pragma unroll
    for (int o = 16; o; o >>= 1) ss += __shfl_xor_sync(0xffffffffu, ss, o);
    if ((tid & 31) == 0) red[tid >> 5] = ss;
    __syncthreads();
    if (tid < 32) {
        float t = (tid < 8) ? red[tid] : 0.f;
        #pragma unroll
        for (int o = 4; o; o >>= 1) t += __shfl_xor_sync(0xffffffffu, t, o);
        if (tid == 0) bval[1] = t;
    }
    __syncthreads();
    const float var = bval[1] * (1.f / 1023.f);
    const float inv = 1.f / (sqrtf(var) + 1e-6f);

    const float4 gv = ((const float4*)gamma)[tid];
    const float4 bv = ((const float4*)beta)[tid];
    float4 ov;
    ov.x = to_tf32(gv.x * d0 * inv + bv.x);
    ov.y = to_tf32(gv.y * d1 * inv + bv.y);
    ov.z = to_tf32(gv.z * d2 * inv + bv.z);
    ov.w = to_tf32(gv.w * d3 * inv + bv.w);
    ((float4*)(out + (size_t)row * D_MODEL))[tid] = ov;
}

// ---------------------------------------------------------------------------
// tf32 mma.sync GEMM: C[M,N] = A[M,K] @ W[K,N] + bias (+res)(+relu)(+round)
// 128x128 tile, BK=32, 256 threads (8 warps of 64x32), cp.async double-buffer.
// flags: bit0 = relu, bit1 = round output to tf32
// ---------------------------------------------------------------------------
#define AS_STRIDE 36
#define BS_STRIDE 132
#define AS_BUF (128 * AS_STRIDE)
#define BS_BUF (32 * BS_STRIDE)
#define GM_SMEM ((2 * AS_BUF + 2 * BS_BUF) * 4)

__global__ void __launch_bounds__(256, 2)
gemm_mma(const float* __restrict__ A, const float* __restrict__ W,
         const float* __restrict__ bias, const float* __restrict__ res,
         float* __restrict__ C, int M, int N, int K, int flags)
{
    extern __shared__ float smf[];
    float* Asf = smf;
    float* Bsf = smf + 2 * AS_BUF;
    const uint32_t aSm = smem_u32(Asf);
    const uint32_t bSm = smem_u32(Bsf);

    const int tid = threadIdx.x;
    const int lane = tid & 31;
    const int wid = tid >> 5;
    const int g  = lane >> 2;
    const int tg = lane & 3;
    const int wm = (wid & 1) * 64;
    const int wn = (wid >> 1) * 32;
    const int row0 = blockIdx.y * 128;
    const int col0 = blockIdx.x * 128;

    const int ar[4] = { tid >> 3, (tid + 256) >> 3, (tid + 512) >> 3, (tid + 768) >> 3 };
    const int aq = (tid & 7) * 4;
    const int bkr[4] = { tid >> 5, (tid + 256) >> 5, (tid + 512) >> 5, (tid + 768) >> 5 };
    const int bq = (tid & 31) * 4;

    float acc[4][4][4] = {};
    const int NC = K >> 5;

    {
        #pragma unroll
        for (int f = 0; f < 4; ++f) {
            CP_ASYNC16(aSm + (uint32_t)(ar[f] * AS_STRIDE + aq) * 4,
                       A + (size_t)(row0 + ar[f]) * K + aq);
            CP_ASYNC16(bSm + (uint32_t)(bkr[f] * BS_STRIDE + bq) * 4,
                       W + (size_t)bkr[f] * N + col0 + bq);
        }
        CP_COMMIT();
    }

    for (int c = 0; c < NC; ++c) {
        const int buf = c & 1;
        __syncthreads();
        if (c + 1 < NC) {
            const int kc = (c + 1) << 5;
            const uint32_t aOff = aSm + (uint32_t)(((c + 1) & 1) * AS_BUF) * 4;
            const uint32_t bOff = bSm + (uint32_t)(((c + 1) & 1) * BS_BUF) * 4;
            #pragma unroll
            for (int f = 0; f < 4; ++f) {
                CP_ASYNC16(aOff + (uint32_t)(ar[f] * AS_STRIDE + aq) * 4,
                           A + (size_t)(row0 + ar[f]) * K + kc + aq);
                CP_ASYNC16(bOff + (uint32_t)(bkr[f] * BS_STRIDE + bq) * 4,
                           W + (size_t)(kc + bkr[f]) * N + col0 + bq);
            }
            CP_COMMIT();
            CP_WAIT1();
        } else {
            CP_WAIT0();
        }
        __syncthreads();

        const uint32_t* Au = (const uint32_t*)(Asf + buf * AS_BUF);
        const uint32_t* Bu = (const uint32_t*)(Bsf + buf * BS_BUF);

        #pragma unroll
        for (int s = 0; s < 4; ++s) {
            const int k0 = s * 8;
            uint32_t a[4][4], b[4][2];
            #pragma unroll
            for (int mt = 0; mt < 4; ++mt) {
                const int r = wm + mt * 16 + g;
                a[mt][0] = Au[r * AS_STRIDE + k0 + tg];
                a[mt][1] = Au[(r + 8) * AS_STRIDE + k0 + tg];
                a[mt][2] = Au[r * AS_STRIDE + k0 + tg + 4];
                a[mt][3] = Au[(r + 8) * AS_STRIDE + k0 + tg + 4];
            }
            #pragma unroll
            for (int nt = 0; nt < 4; ++nt) {
                const int ncol = wn + nt * 8 + g;
                b[nt][0] = Bu[(k0 + tg) * BS_STRIDE + ncol];
                b[nt][1] = Bu[(k0 + tg + 4) * BS_STRIDE + ncol];
            }
            #pragma unroll
            for (int mt = 0; mt < 4; ++mt)
                #pragma unroll
                for (int nt = 0; nt < 4; ++nt)
                    mma_tf32(acc[mt][nt], a[mt][0], a[mt][1], a[mt][2], a[mt][3],
                             b[nt][0], b[nt][1]);
        }
    }

    const int relu = flags & 1;
    const int rnd  = flags & 2;
    #pragma unroll
    for (int mt = 0; mt < 4; ++mt) {
        const int r0 = row0 + wm + mt * 16 + g;
        #pragma unroll
        for (int nt = 0; nt < 4; ++nt) {
            const int cc = col0 + wn + nt * 8 + tg * 2;
            float2 bv = *(const float2*)(bias + cc);
            float v0 = acc[mt][nt][0] + bv.x;
            float v1 = acc[mt][nt][1] + bv.y;
            float v2 = acc[mt][nt][2] + bv.x;
            float v3 = acc[mt][nt][3] + bv.y;
            if (res) {
                float2 r1 = *(const float2*)(res + (size_t)r0 * N + cc);
                float2 r2 = *(const float2*)(res + (size_t)(r0 + 8) * N + cc);
                v0 += r1.x; v1 += r1.y; v2 += r2.x; v3 += r2.y;
            }
            if (relu) {
                v0 = fmaxf(v0, 0.f); v1 = fmaxf(v1, 0.f);
                v2 = fmaxf(v2, 0.f); v3 = fmaxf(v3, 0.f);
            }
            if (rnd) {
                v0 = to_tf32(v0); v1 = to_tf32(v1);
                v2 = to_tf32(v2); v3 = to_tf32(v3);
            }
            *(float2*)(C + (size_t)r0 * N + cc) = make_float2(v0, v1);
            *(float2*)(C + (size_t)(r0 + 8) * N + cc) = make_float2(v2, v3);
        }
    }
}

// ---------------------------------------------------------------------------
// Tensor-core flash attention: Br=128, Bc=64, d=64, 8 warps (16 rows each).
// grid (SEQ/128, HEADS, BATCH), 256 threads. Input: packed QKV [rows][3072].
// Output ctx [rows][1024] rounded to tf32.
// ---------------------------------------------------------------------------
#define AST 68
#define A_QS 0
#define A_KS (128 * AST)
#define A_VS (A_KS + 64 * AST)
#define A_SS (A_VS + 64 * AST)
#define A_MB (A_SS + 128 * AST)
#define ATT_SMEM ((A_MB + 64) * 4)

__global__ void __launch_bounds__(256, 2)
attn_mma(const float* __restrict__ QKV, const int* __restrict__ mask,
         float* __restrict__ O)
{
    extern __shared__ float smf[];
    float* Qs = smf + A_QS;
    float* Ks = smf + A_KS;
    float* Vs = smf + A_VS;
    float* Ss = smf + A_SS;
    float* Mb = smf + A_MB;
    const uint32_t* Qu = (const uint32_t*)Qs;
    const uint32_t* Ku = (const uint32_t*)Ks;
    const uint32_t* Vu = (const uint32_t*)Vs;
    const uint32_t* Su = (const uint32_t*)Ss;

    const int qt = blockIdx.x;
    const int h  = blockIdx.y;
    const int b  = blockIdx.z;
    const int tid = threadIdx.x;
    const int lane = tid & 31;
    const int wid = tid >> 5;
    const int g  = lane >> 2;
    const int tg = lane & 3;
    const int w16 = wid * 16;

    const size_t rowBase = (size_t)(b * SEQ + qt * 128);
    const int hcol = h * DK;

    // load Q (128x64), scale by 1/8, round to tf32
    #pragma unroll
    for (int f = 0; f < 8; ++f) {
        const int linear = tid + 256 * f;
        const int row = linear >> 4, c4 = (linear & 15) * 4;
        float4 v = *(const float4*)(QKV + (rowBase + row) * QKV_N + hcol + c4);
        v.x = to_tf32(v.x * 0.125f); v.y = to_tf32(v.y * 0.125f);
        v.z = to_tf32(v.z * 0.125f); v.w = to_tf32(v.w * 0.125f);
        *(float4*)&Qs[row * AST + c4] = v;
    }

    float m0 = -INFINITY, m1 = -INFINITY, l0 = 0.f, l1 = 0.f;
    float acc_o[8][4] = {};

    for (int j = 0; j < SEQ / 64; ++j) {
        __syncthreads();
        // load K, V tiles (64x64 each), round to tf32
        #pragma unroll
        for (int f = 0; f < 4; ++f) {
            const int linear = tid + 256 * f;
            const int row = linear >> 4, c4 = (linear & 15) * 4;
            const size_t gro = ((size_t)(b * SEQ + j * 64 + row)) * QKV_N + hcol + c4;
            float4 kv = *(const float4*)(QKV + gro + D_MODEL);
            float4 vv = *(const float4*)(QKV + gro + 2 * D_MODEL);
            kv.x = to_tf32(kv.x); kv.y = to_tf32(kv.y);
            kv.z = to_tf32(kv.z); kv.w = to_tf32(kv.w);
            vv.x = to_tf32(vv.x); vv.y = to_tf32(vv.y);
            vv.z = to_tf32(vv.z); vv.w = to_tf32(vv.w);
            *(float4*)&Ks[row * AST + c4] = kv;
            *(float4*)&Vs[row * AST + c4] = vv;
        }
        if (tid < 64)
            Mb[tid] = (mask[b * SEQ + j * 64 + tid] == 0) ? -1.0e9f : 0.f;
        __syncthreads();

        // S = Q @ K^T  (per-warp 16x64)
        float sacc[8][4] = {};
        #pragma unroll
        for (int ks = 0; ks < 8; ++ks) {
            const int k0 = ks * 8;
            const uint32_t a0 = Qu[(w16 + g) * AST + k0 + tg];
            const uint32_t a1 = Qu[(w16 + g + 8) * AST + k0 + tg];
            const uint32_t a2 = Qu[(w16 + g) * AST + k0 + tg + 4];
            const uint32_t a3 = Qu[(w16 + g + 8) * AST + k0 + tg + 4];
            #pragma unroll
            for (int nt = 0; nt < 8; ++nt) {
                const uint32_t b0 = Ku[(nt * 8 + g) * AST + k0 + tg];
                const uint32_t b1 = Ku[(nt * 8 + g) * AST + k0 + tg + 4];
                mma_tf32(sacc[nt], a0, a1, a2, a3, b0, b1);
            }
        }

        // mask + online softmax (rows g, g+8 per thread)
        float mx0 = -INFINITY, mx1 = -INFINITY;
        #pragma unroll
        for (int nt = 0; nt < 8; ++nt) {
            const float mb0 = Mb[nt * 8 + 2 * tg];
            const float mb1 = Mb[nt * 8 + 2 * tg + 1];
            sacc[nt][0] += mb0; sacc[nt][1] += mb1;
            sacc[nt][2] += mb0; sacc[nt][3] += mb1;
            mx0 = fmaxf(mx0, fmaxf(sacc[nt][0], sacc[nt][1]));
            mx1 = fmaxf(mx1, fmaxf(sacc[nt][2], sacc[nt][3]));
        }
        mx0 = fmaxf(mx0, __shfl_xor_sync(0xffffffffu, mx0, 1));
        mx0 = fmaxf(mx0, __shfl_xor_sync(0xffffffffu, mx0, 2));
        mx1 = fmaxf(mx1, __shfl_xor_sync(0xffffffffu, mx1, 1));
        mx1 = fmaxf(mx1, __shfl_xor_sync(0xffffffffu, mx1, 2));

        const float mn0 = fmaxf(m0, mx0), mn1 = fmaxf(m1, mx1);
        const float sc0 = expf(m0 - mn0), sc1 = expf(m1 - mn1);
        float sum0 = 0.f, sum1 = 0.f;
        #pragma unroll
        for (int nt = 0; nt < 8; ++nt) {
            float p0 = to_tf32(expf(sacc[nt][0] - mn0));
            float p1 = to_tf32(expf(sacc[nt][1] - mn0));
            float p2 = to_tf32(expf(sacc[nt][2] - mn1));
            float p3 = to_tf32(expf(sacc[nt][3] - mn1));
            sum0 += p0 + p1; sum1 += p2 + p3;
            sacc[nt][0] = p0; sacc[nt][1] = p1; sacc[nt][2] = p2; sacc[nt][3] = p3;
        }
        sum0 += __shfl_xor_sync(0xffffffffu, sum0, 1);
        sum0 += __shfl_xor_sync(0xffffffffu, sum0, 2);
        sum1 += __shfl_xor_sync(0xffffffffu, sum1, 1);
        sum1 += __shfl_xor_sync(0xffffffffu, sum1, 2);
        l0 = l0 * sc0 + sum0; l1 = l1 * sc1 + sum1;
        m0 = mn0; m1 = mn1;

        #pragma unroll
        for (int nt = 0; nt < 8; ++nt) {
            acc_o[nt][0] *= sc0; acc_o[nt][1] *= sc0;
            acc_o[nt][2] *= sc1; acc_o[nt][3] *= sc1;
        }

        // stage P to warp-private Ss rows
        #pragma unroll
        for (int nt = 0; nt < 8; ++nt) {
            *(float2*)&Ss[(w16 + g) * AST + nt * 8 + 2 * tg] =
                make_float2(sacc[nt][0], sacc[nt][1]);
            *(float2*)&Ss[(w16 + g + 8) * AST + nt * 8 + 2 * tg] =
                make_float2(sacc[nt][2], sacc[nt][3]);
        }
        __syncwarp();

        // O += P @ V
        #pragma unroll
        for (int ks = 0; ks < 8; ++ks) {
            const int k0 = ks * 8;
            const uint32_t a0 = Su[(w16 + g) * AST + k0 + tg];
            const uint32_t a1 = Su[(w16 + g + 8) * AST + k0 + tg];
            const uint32_t a2 = Su[(w16 + g) * AST + k0 + tg + 4];
            const uint32_t a3 = Su[(w16 + g + 8) * AST + k0 + tg + 4];
            #pragma unroll
            for (int nt = 0; nt < 8; ++nt) {
                const uint32_t b0 = Vu[(k0 + tg) * AST + nt * 8 + g];
                const uint32_t b1 = Vu[(k0 + tg + 4) * AST + nt * 8 + g];
                mma_tf32(acc_o[nt], a0, a1, a2, a3, b0, b1);
            }
        }
        __syncwarp();
    }

    // epilogue: divide by l, round to tf32 (feeds wo GEMM), write ctx
    const float il0 = 1.f / l0, il1 = 1.f / l1;
    #pragma unroll
    for (int nt = 0; nt < 8; ++nt) {
        const int cc = hcol + nt * 8 + 2 * tg;
        float* o0 = O + (rowBase + w16 + g) * D_MODEL + cc;
        float* o1 = O + (rowBase + w16 + g + 8) * D_MODEL + cc;
        *(float2*)o0 = make_float2(to_tf32(acc_o[nt][0] * il0), to_tf32(acc_o[nt][1] * il0));
        *(float2*)o1 = make_float2(to_tf32(acc_o[nt][2] * il1), to_tf32(acc_o[nt][3] * il1));
    }
}

// ---------------------------------------------------------------------------
extern "C" void kernel_launch(void* const* d_in, const int* in_sizes, int n_in,
                              void* d_out, int out_size)
{
    const float* x    = (const float*)d_in[0];
    const int*   mask = (const int*)  d_in[1];
    const float* wq   = (const float*)d_in[2];
    const float* wk   = (const float*)d_in[3];
    const float* wv   = (const float*)d_in[4];
    const float* wo   = (const float*)d_in[5];
    const float* bq   = (const float*)d_in[6];
    const float* bk   = (const float*)d_in[7];
    const float* bv   = (const float*)d_in[8];
    const float* bo   = (const float*)d_in[9];
    const float* w1   = (const float*)d_in[10];
    const float* b1   = (const float*)d_in[11];
    const float* w2   = (const float*)d_in[12];
    const float* b2   = (const float*)d_in[13];
    const float* ln1g = (const float*)d_in[14];
    const float* ln1b = (const float*)d_in[15];
    const float* ln2g = (const float*)d_in[16];
    const float* ln2b = (const float*)d_in[17];
    float* out = (float*)d_out;

    void *p;
    cudaGetSymbolAddress(&p, g_h);    float* h    = (float*)p;
    cudaGetSymbolAddress(&p, g_qkv);  float* qkv  = (float*)p;
    cudaGetSymbolAddress(&p, g_ctx);  float* ctx  = (float*)p;
    cudaGetSymbolAddress(&p, g_x1);   float* x1   = (float*)p;
    cudaGetSymbolAddress(&p, g_h2);   float* h2   = (float*)p;
    cudaGetSymbolAddress(&p, g_ff1);  float* ff1  = (float*)p;
    cudaGetSymbolAddress(&p, g_wqkv); float* wqkv = (float*)p;
    cudaGetSymbolAddress(&p, g_bqkv); float* bqkv = (float*)p;
    cudaGetSymbolAddress(&p, g_wor);  float* wor  = (float*)p;
    cudaGetSymbolAddress(&p, g_w1r);  float* w1r  = (float*)p;
    cudaGetSymbolAddress(&p, g_w2r);  float* w2r  = (float*)p;

    cudaFuncSetAttribute(attn_mma, cudaFuncAttributeMaxDynamicSharedMemorySize, ATT_SMEM);
    cudaFuncSetAttribute(gemm_mma, cudaFuncAttributeMaxDynamicSharedMemorySize, GM_SMEM);

    // 0) round/pack weights
    {
        const int TPB = 256;
        const int n1 = D_MODEL * D_MODEL / 4;
        const int n2 = D_MODEL * FF_DIM / 4;
        round_pack_kernel<<<(n1 + TPB - 1) / TPB, TPB>>>(wq, wqkv, D_MODEL, D_MODEL, QKV_N, 0);
        round_pack_kernel<<<(n1 + TPB - 1) / TPB, TPB>>>(wk, wqkv, D_MODEL, D_MODEL, QKV_N, D_MODEL);
        round_pack_kernel<<<(n1 + TPB - 1) / TPB, TPB>>>(wv, wqkv, D_MODEL, D_MODEL, QKV_N, 2 * D_MODEL);
        pack_bias_kernel<<<4, 256>>>(bq, bk, bv, bqkv);
        round_tf32_kernel<<<(n1 + TPB - 1) / TPB, TPB>>>(wo, wor, n1);
        round_tf32_kernel<<<(n2 + TPB - 1) / TPB, TPB>>>(w1, w1r, n2);
        round_tf32_kernel<<<(n2 + TPB - 1) / TPB, TPB>>>(w2, w2r, n2);
    }

    // 1) h = LN1(x)
    ln_kernel<<<MROWS, 256>>>(x, ln1g, ln1b, h);

    // 2) fused QKV projection: qkv = h @ wqkv + bqkv
    {
        dim3 grid(QKV_N / 128, MROWS / 128);
        gemm_mma<<<grid, 256, GM_SMEM>>>(h, wqkv, bqkv, nullptr, qkv, MROWS, QKV_N, D_MODEL, 0);
    }

    // 3) attention -> ctx
    {
        dim3 grid(SEQ / 128, HEADS, BATCH);
        attn_mma<<<grid, 256, ATT_SMEM>>>(qkv, mask, ctx);
    }

    // 4) x1 = x + ctx @ wo + bo
    {
        dim3 grid(D_MODEL / 128, MROWS / 128);
        gemm_mma<<<grid, 256, GM_SMEM>>>(ctx, wor, bo, x, x1, MROWS, D_MODEL, D_MODEL, 0);
    }

    // 5) h2 = LN2(x1)
    ln_kernel<<<MROWS, 256>>>(x1, ln2g, ln2b, h2);

    // 6) ff1 = relu(h2 @ w1 + b1), rounded
    {
        dim3 grid(FF_DIM / 128, MROWS / 128);
        gemm_mma<<<grid, 256, GM_SMEM>>>(h2, w1r, b1, nullptr, ff1, MROWS, FF_DIM, D_MODEL, 3);
    }

    // 7) out = x1 + ff1 @ w2 + b2
    {
        dim3 grid(D_MODEL / 128, MROWS / 128);
        gemm_mma<<<grid, 256, GM_SMEM>>>(ff1, w2r, b2, x1, out, MROWS, D_MODEL, FF_DIM, 0);
    }
}

// round 6
// speedup vs baseline: 6.7735x; 2.0277x over previous
#include <cuda_runtime.h>
#include <cuda_fp16.h>
#include <math.h>
#include <stdint.h>

// ---------------------------------------------------------------------------
// EncoderLayer round 5: fp16-operand mma.sync (m16n8k16) for GEMMs+attention,
// fp32 accumulation/residuals. B=2,S=2048,D=1024,H=16,DK=64,FF=4096.
// ---------------------------------------------------------------------------

#define D_MODEL 1024
#define SEQ     2048
#define BATCH   2
#define HEADS   16
#define DK      64
#define FF_DIM  4096
#define MROWS   (BATCH * SEQ)      // 4096
#define QKV_N   (3 * D_MODEL)      // 3072

// Scratch (allocation-free device globals)
__device__ __half g_h   [MROWS * D_MODEL];
__device__ __half g_qkv [(size_t)MROWS * QKV_N];
__device__ __half g_ctx [MROWS * D_MODEL];
__device__ float  g_x1  [MROWS * D_MODEL];
__device__ __half g_h2  [MROWS * D_MODEL];
__device__ __half g_ff1 [(size_t)MROWS * FF_DIM];
// fp16 weights
__device__ __half g_wqkv[(size_t)D_MODEL * QKV_N];
__device__ float  g_bqkv[QKV_N];
__device__ __half g_woh [D_MODEL * D_MODEL];
__device__ __half g_w1h [D_MODEL * FF_DIM];
__device__ __half g_w2h [FF_DIM * D_MODEL];

__device__ __forceinline__ uint32_t smem_u32(const void* p) {
    uint32_t a;
    asm("{ .reg .u64 t; cvta.to.shared.u64 t, %1; cvt.u32.u64 %0, t; }" : "=r"(a) : "l"(p));
    return a;
}
__device__ __forceinline__ void ldsm4(uint32_t* r, uint32_t a) {
    asm volatile("ldmatrix.sync.aligned.m8n8.x4.shared.b16 {%0,%1,%2,%3}, [%4];"
        : "=r"(r[0]), "=r"(r[1]), "=r"(r[2]), "=r"(r[3]) : "r"(a));
}
__device__ __forceinline__ void ldsm4t(uint32_t* r, uint32_t a) {
    asm volatile("ldmatrix.sync.aligned.m8n8.x4.trans.shared.b16 {%0,%1,%2,%3}, [%4];"
        : "=r"(r[0]), "=r"(r[1]), "=r"(r[2]), "=r"(r[3]) : "r"(a));
}
__device__ __forceinline__ void mma_f16(float* c, const uint32_t* a,
                                        uint32_t b0, uint32_t b1) {
    asm volatile(
        "mma.sync.aligned.m16n8k16.row.col.f32.f16.f16.f32 "
        "{%0,%1,%2,%3}, {%4,%5,%6,%7}, {%8,%9}, {%0,%1,%2,%3};"
        : "+f"(c[0]), "+f"(c[1]), "+f"(c[2]), "+f"(c[3])
        : "r"(a[0]), "r"(a[1]), "r"(a[2]), "r"(a[3]), "r"(b0), "r"(b1));
}
#define CP_ASYNC16(sa, gp) \
    asm volatile("cp.async.cg.shared.global [%0], [%1], 16;" :: "r"(sa), "l"(gp) : "memory")
#define CP_COMMIT() asm volatile("cp.async.commit_group;" ::: "memory")
#define CP_WAIT0()  asm volatile("cp.async.wait_group 0;" ::: "memory")
#define CP_WAIT1()  asm volatile("cp.async.wait_group 1;" ::: "memory")

// ---------------------------------------------------------------------------
// Prepass: fp32 -> fp16 weight conversion (+QKV pack, +bias pack)
// ---------------------------------------------------------------------------
__global__ void cvt_h_kernel(const float* __restrict__ in, __half* __restrict__ out, int n4)
{
    const int i = blockIdx.x * blockDim.x + threadIdx.x;
    if (i < n4) {
        float4 v = ((const float4*)in)[i];
        ((__half2*)out)[i * 2 + 0] = __floats2half2_rn(v.x, v.y);
        ((__half2*)out)[i * 2 + 1] = __floats2half2_rn(v.z, v.w);
    }
}
__global__ void cvt_pack_kernel(const float* __restrict__ in, __half* __restrict__ out,
                                int rows, int nin, int ntot, int colOff)
{
    const int n4r = nin >> 2;
    const int i = blockIdx.x * blockDim.x + threadIdx.x;
    if (i < rows * n4r) {
        const int k = i / n4r, n4 = i - k * n4r;
        float4 v = ((const float4*)in)[i];
        __half2* o = (__half2*)(out + (size_t)k * ntot + colOff + n4 * 4);
        o[0] = __floats2half2_rn(v.x, v.y);
        o[1] = __floats2half2_rn(v.z, v.w);
    }
}
__global__ void pack_bias_kernel(const float* __restrict__ bq, const float* __restrict__ bk,
                                 const float* __restrict__ bv, float* __restrict__ out)
{
    const int i = blockIdx.x * blockDim.x + threadIdx.x;
    if (i < D_MODEL) {
        out[i] = bq[i];
        out[D_MODEL + i] = bk[i];
        out[2 * D_MODEL + i] = bv[i];
    }
}

// ---------------------------------------------------------------------------
// LayerNorm -> fp16 output
// ---------------------------------------------------------------------------
__global__ void ln_kernel(const float* __restrict__ x,
                          const float* __restrict__ gamma,
                          const float* __restrict__ beta,
                          __half* __restrict__ out)
{
    __shared__ float red[8];
    __shared__ float bval[2];
    const int row = blockIdx.x;
    const int tid = threadIdx.x;

    const float4 xv = ((const float4*)(x + (size_t)row * D_MODEL))[tid];

    float s = xv.x + xv.y + xv.z + xv.w;
    #pragma unroll
    for (int o = 16; o; o >>= 1) s += __shfl_xor_sync(0xffffffffu, s, o);
    if ((tid & 31) == 0) red[tid >> 5] = s;
    __syncthreads();
    if (tid < 32) {
        float t = (tid < 8) ? red[tid] : 0.f;
        #pragma unroll
        for (int o = 4; o; o >>= 1) t += __shfl_xor_sync(0xffffffffu, t, o);
        if (tid == 0) bval[0] = t;
    }
    __syncthreads();
    const float mean = bval[0] * (1.f / 1024.f);

    const float d0 = xv.x - mean, d1 = xv.y - mean, d2 = xv.z - mean, d3 = xv.w - mean;
    float ss = d0 * d0 + d1 * d1 + d2 * d2 + d3 * d3;
    #pragma unroll
    for (int o = 16; o; o >>= 1) ss += __shfl_xor_sync(0xffffffffu, ss, o);
    if ((tid & 31) == 0) red[tid >> 5] = ss;
    __syncthreads();
    if (tid < 32) {
        float t = (tid < 8) ? red[tid] : 0.f;
        #pragma unroll
        for (int o = 4; o; o >>= 1) t += __shfl_xor_sync(0xffffffffu, t, o);
        if (tid == 0) bval[1] = t;
    }
    __syncthreads();
    const float var = bval[1] * (1.f / 1023.f);
    const float inv = 1.f / (sqrtf(var) + 1e-6f);

    const float4 gv = ((const float4*)gamma)[tid];
    const float4 bv = ((const float4*)beta)[tid];
    __half2* op = (__half2*)(out + (size_t)row * D_MODEL) + tid * 2;
    op[0] = __floats2half2_rn(gv.x * d0 * inv + bv.x, gv.y * d1 * inv + bv.y);
    op[1] = __floats2half2_rn(gv.z * d2 * inv + bv.z, gv.w * d3 * inv + bv.w);
}

// ---------------------------------------------------------------------------
// fp16 mma GEMM: C[M,N] = A[M,K] @ W[K,N] + bias (+res)(+relu)
// Output: Ch (half) if non-null, else Cf (float). 128x128 tile, BK=32.
// ---------------------------------------------------------------------------
#define GH_AS 40
#define GH_BS 136
#define GH_ABUF (128 * GH_AS)
#define GH_BBUF (32 * GH_BS)
#define GH_SMEM ((2 * GH_ABUF + 2 * GH_BBUF) * 2)

__global__ void __launch_bounds__(256, 2)
gemm_h(const __half* __restrict__ A, const __half* __restrict__ W,
       const float* __restrict__ bias, const float* __restrict__ res,
       float* __restrict__ Cf, __half* __restrict__ Ch,
       int M, int N, int K, int relu)
{
    extern __shared__ __half smh[];
    __half* Ash = smh;
    __half* Bsh = smh + 2 * GH_ABUF;
    const uint32_t aSm = smem_u32(Ash);
    const uint32_t bSm = smem_u32(Bsh);

    const int tid = threadIdx.x;
    const int lane = tid & 31;
    const int wid = tid >> 5;
    const int g  = lane >> 2;
    const int tg = lane & 3;
    const int wm = (wid & 1) * 64;
    const int wn = (wid >> 1) * 32;
    const int row0 = blockIdx.y * 128;
    const int col0 = blockIdx.x * 128;

    // ldmatrix lane geometry (shared by non-trans A and trans B)
    const int lr = (lane & 7) + ((lane & 8) ? 8 : 0);
    const int lc = (lane & 16) ? 8 : 0;

    const int arow[2] = { tid >> 2, (tid + 256) >> 2 };
    const int aseg = (tid & 3) * 8;
    const int brow[2] = { tid >> 4, (tid + 256) >> 4 };
    const int bseg = (tid & 15) * 8;

    float acc[4][4][4] = {};
    const int NC = K >> 5;

    {
        #pragma unroll
        for (int f = 0; f < 2; ++f) {
            CP_ASYNC16(aSm + (uint32_t)(arow[f] * GH_AS + aseg) * 2,
                       A + (size_t)(row0 + arow[f]) * K + aseg);
            CP_ASYNC16(bSm + (uint32_t)(brow[f] * GH_BS + bseg) * 2,
                       W + (size_t)brow[f] * N + col0 + bseg);
        }
        CP_COMMIT();
    }

    for (int c = 0; c < NC; ++c) {
        const int buf = c & 1;
        __syncthreads();
        if (c + 1 < NC) {
            const int kc = (c + 1) << 5;
            const uint32_t aOff = aSm + (uint32_t)(((c + 1) & 1) * GH_ABUF) * 2;
            const uint32_t bOff = bSm + (uint32_t)(((c + 1) & 1) * GH_BBUF) * 2;
            #pragma unroll
            for (int f = 0; f < 2; ++f) {
                CP_ASYNC16(aOff + (uint32_t)(arow[f] * GH_AS + aseg) * 2,
                           A + (size_t)(row0 + arow[f]) * K + kc + aseg);
                CP_ASYNC16(bOff + (uint32_t)(brow[f] * GH_BS + bseg) * 2,
                           W + (size_t)(kc + brow[f]) * N + col0 + bseg);
            }
            CP_COMMIT();
            CP_WAIT1();
        } else {
            CP_WAIT0();
        }
        __syncthreads();

        const uint32_t aBase = aSm + (uint32_t)(buf * GH_ABUF) * 2;
        const uint32_t bBase = bSm + (uint32_t)(buf * GH_BBUF) * 2;

        #pragma unroll
        for (int ks = 0; ks < 2; ++ks) {
            uint32_t aF[4][4];
            #pragma unroll
            for (int mt = 0; mt < 4; ++mt)
                ldsm4(aF[mt], aBase + (uint32_t)((wm + mt * 16 + lr) * GH_AS + ks * 16 + lc) * 2);
            #pragma unroll
            for (int ntp = 0; ntp < 2; ++ntp) {
                uint32_t bF[4];
                ldsm4t(bF, bBase + (uint32_t)((ks * 16 + lr) * GH_BS + wn + ntp * 16 + lc) * 2);
                #pragma unroll
                for (int mt = 0; mt < 4; ++mt) {
                    mma_f16(acc[mt][2 * ntp],     aF[mt], bF[0], bF[1]);
                    mma_f16(acc[mt][2 * ntp + 1], aF[mt], bF[2], bF[3]);
                }
            }
        }
    }

    #pragma unroll
    for (int mt = 0; mt < 4; ++mt) {
        const int r0 = row0 + wm + mt * 16 + g;
        #pragma unroll
        for (int nt = 0; nt < 4; ++nt) {
            const int cc = col0 + wn + nt * 8 + tg * 2;
            float2 bv = *(const float2*)(bias + cc);
            float v0 = acc[mt][nt][0] + bv.x;
            float v1 = acc[mt][nt][1] + bv.y;
            float v2 = acc[mt][nt][2] + bv.x;
            float v3 = acc[mt][nt][3] + bv.y;
            if (res) {
                float2 r1 = *(const float2*)(res + (size_t)r0 * N + cc);
                float2 r2 = *(const float2*)(res + (size_t)(r0 + 8) * N + cc);
                v0 += r1.x; v1 += r1.y; v2 += r2.x; v3 += r2.y;
            }
            if (relu) {
                v0 = fmaxf(v0, 0.f); v1 = fmaxf(v1, 0.f);
                v2 = fmaxf(v2, 0.f); v3 = fmaxf(v3, 0.f);
            }
            if (Ch) {
                *(__half2*)(Ch + (size_t)r0 * N + cc)       = __floats2half2_rn(v0, v1);
                *(__half2*)(Ch + (size_t)(r0 + 8) * N + cc) = __floats2half2_rn(v2, v3);
            } else {
                *(float2*)(Cf + (size_t)r0 * N + cc)       = make_float2(v0, v1);
                *(float2*)(Cf + (size_t)(r0 + 8) * N + cc) = make_float2(v2, v3);
            }
        }
    }
}

// ---------------------------------------------------------------------------
// fp16 tensor-core flash attention: Br=128, Bc=64, d=64, 8 warps.
// grid (SEQ/128, HEADS, BATCH), 256 threads. P fragment built in registers.
// ---------------------------------------------------------------------------
#define HST 72                         // halves stride
#define AQ_OFF 0
#define AK_OFF (128 * HST)
#define AV_OFF (AK_OFF + 64 * HST)
#define AMB_OFF (AV_OFF + 64 * HST)    // halves index; Mb = floats after
#define ATT_SMEM ((AMB_OFF) * 2 + 64 * 4)

__global__ void __launch_bounds__(256, 2)
attn_h(const __half* __restrict__ QKV, const int* __restrict__ mask,
       __half* __restrict__ O)
{
    extern __shared__ __half smh[];
    __half* Qs = smh + AQ_OFF;
    __half* Ks = smh + AK_OFF;
    __half* Vs = smh + AV_OFF;
    float*  Mb = (float*)(smh + AMB_OFF);
    const uint32_t qSm = smem_u32(Qs);
    const uint32_t kSm = smem_u32(Ks);
    const uint32_t vSm = smem_u32(Vs);

    const int qt = blockIdx.x;
    const int h  = blockIdx.y;
    const int b  = blockIdx.z;
    const int tid = threadIdx.x;
    const int lane = tid & 31;
    const int wid = tid >> 5;
    const int g  = lane >> 2;
    const int tg = lane & 3;
    const int w16 = wid * 16;

    const int lr  = (lane & 7) + ((lane & 8) ? 8 : 0);
    const int lc  = (lane & 16) ? 8 : 0;
    const int lrk = (lane & 7) + ((lane & 16) ? 8 : 0);  // K-fragment geometry
    const int lck = (lane & 8) ? 8 : 0;

    const size_t rowBase = (size_t)(b * SEQ + qt * 128);
    const int hcol = h * DK;

    // load Q tile 128x64 (cp.async, no conversion needed)
    #pragma unroll
    for (int f = 0; f < 4; ++f) {
        const int linear = tid + 256 * f;
        const int row = linear >> 3, seg = (linear & 7) * 8;
        CP_ASYNC16(qSm + (uint32_t)(row * HST + seg) * 2,
                   QKV + (rowBase + row) * QKV_N + hcol + seg);
    }
    CP_COMMIT();
    CP_WAIT0();
    __syncthreads();

    // preload Q fragments (warp-private rows)
    uint32_t qF[4][4];
    #pragma unroll
    for (int ks = 0; ks < 4; ++ks)
        ldsm4(qF[ks], qSm + (uint32_t)((w16 + lr) * HST + ks * 16 + lc) * 2);

    float m0 = -INFINITY, m1 = -INFINITY, l0 = 0.f, l1 = 0.f;
    float acc_o[8][4] = {};

    for (int j = 0; j < SEQ / 64; ++j) {
        __syncthreads();   // previous tile fully consumed
        #pragma unroll
        for (int f = 0; f < 2; ++f) {
            const int linear = tid + 256 * f;
            const int row = linear >> 3, seg = (linear & 7) * 8;
            const size_t gro = ((size_t)(b * SEQ + j * 64 + row)) * QKV_N + hcol + seg;
            CP_ASYNC16(kSm + (uint32_t)(row * HST + seg) * 2, QKV + gro + D_MODEL);
            CP_ASYNC16(vSm + (uint32_t)(row * HST + seg) * 2, QKV + gro + 2 * D_MODEL);
        }
        CP_COMMIT();
        if (tid < 64)
            Mb[tid] = (mask[b * SEQ + j * 64 + tid] == 0) ? -1.0e9f : 0.f;
        CP_WAIT0();
        __syncthreads();

        // S = Q @ K^T
        float sacc[8][4] = {};
        #pragma unroll
        for (int ks = 0; ks < 4; ++ks) {
            #pragma unroll
            for (int ntp = 0; ntp < 4; ++ntp) {
                uint32_t kF[4];
                ldsm4(kF, kSm + (uint32_t)((ntp * 16 + lrk) * HST + ks * 16 + lck) * 2);
                mma_f16(sacc[2 * ntp],     qF[ks], kF[0], kF[1]);
                mma_f16(sacc[2 * ntp + 1], qF[ks], kF[2], kF[3]);
            }
        }

        // scale + mask + online softmax
        float mx0 = -INFINITY, mx1 = -INFINITY;
        #pragma unroll
        for (int nt = 0; nt < 8; ++nt) {
            const float mb0 = Mb[nt * 8 + 2 * tg];
            const float mb1 = Mb[nt * 8 + 2 * tg + 1];
            sacc[nt][0] = sacc[nt][0] * 0.125f + mb0;
            sacc[nt][1] = sacc[nt][1] * 0.125f + mb1;
            sacc[nt][2] = sacc[nt][2] * 0.125f + mb0;
            sacc[nt][3] = sacc[nt][3] * 0.125f + mb1;
            mx0 = fmaxf(mx0, fmaxf(sacc[nt][0], sacc[nt][1]));
            mx1 = fmaxf(mx1, fmaxf(sacc[nt][2], sacc[nt][3]));
        }
        mx0 = fmaxf(mx0, __shfl_xor_sync(0xffffffffu, mx0, 1));
        mx0 = fmaxf(mx0, __shfl_xor_sync(0xffffffffu, mx0, 2));
        mx1 = fmaxf(mx1, __shfl_xor_sync(0xffffffffu, mx1, 1));
        mx1 = fmaxf(mx1, __shfl_xor_sync(0xffffffffu, mx1, 2));

        const float mn0 = fmaxf(m0, mx0), mn1 = fmaxf(m1, mx1);
        const float sc0 = expf(m0 - mn0), sc1 = expf(m1 - mn1);
        float sum0 = 0.f, sum1 = 0.f;
        uint32_t ph[8][2];
        #pragma unroll
        for (int nt = 0; nt < 8; ++nt) {
            const float e0 = expf(sacc[nt][0] - mn0);
            const float e1 = expf(sacc[nt][1] - mn0);
            const float e2 = expf(sacc[nt][2] - mn1);
            const float e3 = expf(sacc[nt][3] - mn1);
            __half2 h01 = __floats2half2_rn(e0, e1);
            __half2 h23 = __floats2half2_rn(e2, e3);
            float2 f01 = __half22float2(h01);
            float2 f23 = __half22float2(h23);
            sum0 += f01.x + f01.y;
            sum1 += f23.x + f23.y;
            ph[nt][0] = *(uint32_t*)&h01;
            ph[nt][1] = *(uint32_t*)&h23;
        }
        sum0 += __shfl_xor_sync(0xffffffffu, sum0, 1);
        sum0 += __shfl_xor_sync(0xffffffffu, sum0, 2);
        sum1 += __shfl_xor_sync(0xffffffffu, sum1, 1);
        sum1 += __shfl_xor_sync(0xffffffffu, sum1, 2);
        l0 = l0 * sc0 + sum0; l1 = l1 * sc1 + sum1;
        m0 = mn0; m1 = mn1;

        #pragma unroll
        for (int nt = 0; nt < 8; ++nt) {
            acc_o[nt][0] *= sc0; acc_o[nt][1] *= sc0;
            acc_o[nt][2] *= sc1; acc_o[nt][3] *= sc1;
        }

        // O += P @ V (P fragment from registers)
        #pragma unroll
        for (int ks = 0; ks < 4; ++ks) {
            uint32_t aP[4];
            aP[0] = ph[2 * ks][0];
            aP[1] = ph[2 * ks][1];
            aP[2] = ph[2 * ks + 1][0];
            aP[3] = ph[2 * ks + 1][1];
            #pragma unroll
            for (int ntp = 0; ntp < 4; ++ntp) {
                uint32_t vF[4];
                ldsm4t(vF, vSm + (uint32_t)((ks * 16 + lr) * HST + ntp * 16 + lc) * 2);
                mma_f16(acc_o[2 * ntp],     aP, vF[0], vF[1]);
                mma_f16(acc_o[2 * ntp + 1], aP, vF[2], vF[3]);
            }
        }
    }

    // epilogue -> ctx (half)
    const float il0 = 1.f / l0, il1 = 1.f / l1;
    #pragma unroll
    for (int nt = 0; nt < 8; ++nt) {
        const int cc = hcol + nt * 8 + 2 * tg;
        *(__half2*)(O + (rowBase + w16 + g) * D_MODEL + cc) =
            __floats2half2_rn(acc_o[nt][0] * il0, acc_o[nt][1] * il0);
        *(__half2*)(O + (rowBase + w16 + g + 8) * D_MODEL + cc) =
            __floats2half2_rn(acc_o[nt][2] * il1, acc_o[nt][3] * il1);
    }
}

// ---------------------------------------------------------------------------
extern "C" void kernel_launch(void* const* d_in, const int* in_sizes, int n_in,
                              void* d_out, int out_size)
{
    const float* x    = (const float*)d_in[0];
    const int*   mask = (const int*)  d_in[1];
    const float* wq   = (const float*)d_in[2];
    const float* wk   = (const float*)d_in[3];
    const float* wv   = (const float*)d_in[4];
    const float* wo   = (const float*)d_in[5];
    const float* bq   = (const float*)d_in[6];
    const float* bk   = (const float*)d_in[7];
    const float* bv   = (const float*)d_in[8];
    const float* bo   = (const float*)d_in[9];
    const float* w1   = (const float*)d_in[10];
    const float* b1   = (const float*)d_in[11];
    const float* w2   = (const float*)d_in[12];
    const float* b2   = (const float*)d_in[13];
    const float* ln1g = (const float*)d_in[14];
    const float* ln1b = (const float*)d_in[15];
    const float* ln2g = (const float*)d_in[16];
    const float* ln2b = (const float*)d_in[17];
    float* out = (float*)d_out;

    void *p;
    cudaGetSymbolAddress(&p, g_h);    __half* h    = (__half*)p;
    cudaGetSymbolAddress(&p, g_qkv);  __half* qkv  = (__half*)p;
    cudaGetSymbolAddress(&p, g_ctx);  __half* ctx  = (__half*)p;
    cudaGetSymbolAddress(&p, g_x1);   float*  x1   = (float*)p;
    cudaGetSymbolAddress(&p, g_h2);   __half* h2   = (__half*)p;
    cudaGetSymbolAddress(&p, g_ff1);  __half* ff1  = (__half*)p;
    cudaGetSymbolAddress(&p, g_wqkv); __half* wqkv = (__half*)p;
    cudaGetSymbolAddress(&p, g_bqkv); float*  bqkv = (float*)p;
    cudaGetSymbolAddress(&p, g_woh);  __half* woh  = (__half*)p;
    cudaGetSymbolAddress(&p, g_w1h);  __half* w1h  = (__half*)p;
    cudaGetSymbolAddress(&p, g_w2h);  __half* w2h  = (__half*)p;

    cudaFuncSetAttribute(attn_h, cudaFuncAttributeMaxDynamicSharedMemorySize, ATT_SMEM);
    cudaFuncSetAttribute(gemm_h, cudaFuncAttributeMaxDynamicSharedMemorySize, GH_SMEM);

    // 0) convert/pack weights to fp16
    {
        const int TPB = 256;
        const int n1 = D_MODEL * D_MODEL / 4;
        const int n2 = D_MODEL * FF_DIM / 4;
        cvt_pack_kernel<<<(n1 + TPB - 1) / TPB, TPB>>>(wq, wqkv, D_MODEL, D_MODEL, QKV_N, 0);
        cvt_pack_kernel<<<(n1 + TPB - 1) / TPB, TPB>>>(wk, wqkv, D_MODEL, D_MODEL, QKV_N, D_MODEL);
        cvt_pack_kernel<<<(n1 + TPB - 1) / TPB, TPB>>>(wv, wqkv, D_MODEL, D_MODEL, QKV_N, 2 * D_MODEL);
        pack_bias_kernel<<<4, 256>>>(bq, bk, bv, bqkv);
        cvt_h_kernel<<<(n1 + TPB - 1) / TPB, TPB>>>(wo, woh, n1);
        cvt_h_kernel<<<(n2 + TPB - 1) / TPB, TPB>>>(w1, w1h, n2);
        cvt_h_kernel<<<(n2 + TPB - 1) / TPB, TPB>>>(w2, w2h, n2);
    }

    // 1) h = LN1(x)
    ln_kernel<<<MROWS, 256>>>(x, ln1g, ln1b, h);

    // 2) fused QKV projection
    {
        dim3 grid(QKV_N / 128, MROWS / 128);
        gemm_h<<<grid, 256, GH_SMEM>>>(h, wqkv, bqkv, nullptr, nullptr, qkv,
                                       MROWS, QKV_N, D_MODEL, 0);
    }

    // 3) attention -> ctx
    {
        dim3 grid(SEQ / 128, HEADS, BATCH);
        attn_h<<<grid, 256, ATT_SMEM>>>(qkv, mask, ctx);
    }

    // 4) x1 = x + ctx @ wo + bo
    {
        dim3 grid(D_MODEL / 128, MROWS / 128);
        gemm_h<<<grid, 256, GH_SMEM>>>(ctx, woh, bo, x, x1, nullptr,
                                       MROWS, D_MODEL, D_MODEL, 0);
    }

    // 5) h2 = LN2(x1)
    ln_kernel<<<MROWS, 256>>>(x1, ln2g, ln2b, h2);

    // 6) ff1 = relu(h2 @ w1 + b1)
    {
        dim3 grid(FF_DIM / 128, MROWS / 128);
        gemm_h<<<grid, 256, GH_SMEM>>>(h2, w1h, b1, nullptr, nullptr, ff1,
                                       MROWS, FF_DIM, D_MODEL, 1);
    }

    // 7) out = x1 + ff1 @ w2 + b2
    {
        dim3 grid(D_MODEL / 128, MROWS / 128);
        gemm_h<<<grid, 256, GH_SMEM>>>(ff1, w2h, b2, x1, out, nullptr,
                                       MROWS, D_MODEL, FF_DIM, 0);
    }
}